// round 1
// baseline (speedup 1.0000x reference)
#include <cuda_runtime.h>
#include <math.h>

#define NN 100000
#define NE 1600000
#define NG 64
#define F1 100
#define F2 200

// ---------------- scratch (static device globals; no allocation) ----------
__device__ float g_dinv[NN];          // deg -> dinv (in place)
__device__ float g_norm[NE];          // per-edge normalization
__device__ float g_aggX[NN * 3];      // A_norm @ x
__device__ float g_h1[NN * F1];       // silu(aggX @ W1 + b1)
__device__ float g_agg1[NN * F1];     // A_norm @ h1
__device__ float g_h2[NN * F2];       // silu(agg1 @ W2 + b2)
__device__ float g_sums[NG * F2];     // pooled sums
__device__ float g_cnt[NG];           // pooled counts

__device__ __forceinline__ float silu(float v) {
    return v / (1.0f + __expf(-v));
}

__device__ __forceinline__ void red_add_v4(float* p, float4 v) {
#if __CUDA_ARCH__ >= 900
    asm volatile("red.global.add.v4.f32 [%0], {%1,%2,%3,%4};"
                 :: "l"(p), "f"(v.x), "f"(v.y), "f"(v.z), "f"(v.w) : "memory");
#else
    atomicAdd(p + 0, v.x); atomicAdd(p + 1, v.y);
    atomicAdd(p + 2, v.z); atomicAdd(p + 3, v.w);
#endif
}

// ---------------- K1: init deg (self-loop weight 1), zero pooled ----------
__global__ void k_init() {
    int i = blockIdx.x * blockDim.x + threadIdx.x;
    if (i < NN) g_dinv[i] = 1.0f;          // self-loop contributes 1 to deg
    if (i < NG * F2) g_sums[i] = 0.0f;
    if (i < NG) g_cnt[i] = 0.0f;
}

// ---------------- K2: deg[col] += w ---------------------------------------
__global__ void k_deg(const int* __restrict__ ei, const float* __restrict__ w) {
    int e = blockIdx.x * blockDim.x + threadIdx.x;
    if (e < NE) atomicAdd(&g_dinv[ei[NE + e]], w[e]);
}

// ---------------- K3: dinv = rsqrt(deg); aggX self-loop init --------------
__global__ void k_dinv(const float* __restrict__ x) {
    int i = blockIdx.x * blockDim.x + threadIdx.x;
    if (i >= NN) return;
    float d = g_dinv[i];
    float di = (d > 0.0f) ? rsqrtf(d) : 0.0f;
    g_dinv[i] = di;
    float s = di * di;               // self-loop norm: dinv*1*dinv
    g_aggX[3 * i + 0] = s * x[3 * i + 0];
    g_aggX[3 * i + 1] = s * x[3 * i + 1];
    g_aggX[3 * i + 2] = s * x[3 * i + 2];
}

// ---------------- K4: norm[e]; scatter x (3 floats/edge) ------------------
__global__ void k_scatterX(const int* __restrict__ ei, const float* __restrict__ w,
                           const float* __restrict__ x) {
    int e = blockIdx.x * blockDim.x + threadIdx.x;
    if (e >= NE) return;
    int row = ei[e];
    int col = ei[NE + e];
    float nm = g_dinv[row] * w[e] * g_dinv[col];
    g_norm[e] = nm;
    atomicAdd(&g_aggX[3 * col + 0], nm * x[3 * row + 0]);
    atomicAdd(&g_aggX[3 * col + 1], nm * x[3 * row + 1]);
    atomicAdd(&g_aggX[3 * col + 2], nm * x[3 * row + 2]);
}

// ---------------- K5: h1 = silu(aggX@W1 + b1); agg1 self-loop init --------
__global__ void k_h1(const float* __restrict__ W1, const float* __restrict__ b1) {
    __shared__ float sW[4 * F1];   // W1 (3x100) then b1 (100)
    for (int t = threadIdx.x; t < 4 * F1; t += blockDim.x)
        sW[t] = (t < 3 * F1) ? W1[t] : b1[t - 3 * F1];
    __syncthreads();
    int idx = blockIdx.x * blockDim.x + threadIdx.x;
    if (idx >= NN * 25) return;
    int n = idx / 25, c4 = idx % 25;
    float a0 = g_aggX[3 * n + 0];
    float a1 = g_aggX[3 * n + 1];
    float a2 = g_aggX[3 * n + 2];
    float di = g_dinv[n];
    float s = di * di;
#pragma unroll
    for (int j = 0; j < 4; j++) {
        int c = c4 * 4 + j;
        float v = fmaf(a0, sW[c], fmaf(a1, sW[F1 + c], fmaf(a2, sW[2 * F1 + c], sW[3 * F1 + c])));
        v = silu(v);
        g_h1[n * F1 + c] = v;
        g_agg1[n * F1 + c] = s * v;     // self-loop term of layer-2 aggregation
    }
}

// ---------------- K6: scatter h1 (100 floats/edge, v4 red) ----------------
__global__ void k_scatter1(const int* __restrict__ ei) {
    int idx = blockIdx.x * blockDim.x + threadIdx.x;
    if (idx >= NE * 25) return;
    int e = idx / 25, c = idx % 25;
    int row = ei[e];
    int col = ei[NE + e];
    float nm = g_norm[e];
    float4 hv = *(const float4*)(g_h1 + row * F1 + c * 4);
    float4 m;
    m.x = nm * hv.x; m.y = nm * hv.y; m.z = nm * hv.z; m.w = nm * hv.w;
    red_add_v4(g_agg1 + col * F1 + c * 4, m);
}

// ---------------- K7: h2 = silu(agg1 @ W2 + b2)  (SGEMM) ------------------
// BM=64 nodes, BN=40 cols, 160 threads, 4x4 micro-tile, K=100 fully staged.
#define BM 64
#define BN 40
#define AS_STRIDE 128   // floats per m-row (32 float4 chunks; allows 5-bit xor swizzle)

__global__ void k_gemm2(const float* __restrict__ W2, const float* __restrict__ b2) {
    __shared__ float As[BM * AS_STRIDE];   // [m][k], f4-chunk xor-swizzled
    __shared__ float Bs[F1 * BN];          // [k][c]
    int tid = threadIdx.x;
    int n0 = blockIdx.x * BM;
    int cb = blockIdx.y * BN;

    // load A tile (coalesced along k; swizzled f4 store)
    for (int t = tid; t < BM * 25; t += 160) {
        int m = t / 25, k4 = t % 25;
        int n = n0 + m;
        float4 v = make_float4(0.f, 0.f, 0.f, 0.f);
        if (n < NN) v = *(const float4*)(g_agg1 + n * F1 + k4 * 4);
        int chunk = k4 ^ ((m >> 2) & 7);
        *(float4*)(As + m * AS_STRIDE + chunk * 4) = v;
    }
    // load B tile
    for (int t = tid; t < F1 * 10; t += 160) {
        int k = t / 10, c4 = t % 10;
        *(float4*)(Bs + k * BN + c4 * 4) = *(const float4*)(W2 + k * F2 + cb + c4 * 4);
    }
    __syncthreads();

    int tidx = tid % 10;  // col group
    int tidy = tid / 10;  // row group (0..15)
    float acc[4][4] = {};

#pragma unroll 5
    for (int k4 = 0; k4 < 25; k4++) {
        float4 a[4];
        int chunk = (k4 ^ (tidy & 7)) << 2;
#pragma unroll
        for (int i = 0; i < 4; i++) {
            int m = tidy * 4 + i;
            a[i] = *(const float4*)(As + m * AS_STRIDE + chunk);
        }
#pragma unroll
        for (int kk = 0; kk < 4; kk++) {
            float4 bv = *(const float4*)(Bs + (k4 * 4 + kk) * BN + tidx * 4);
#pragma unroll
            for (int i = 0; i < 4; i++) {
                float av = (&a[i].x)[kk];
                acc[i][0] = fmaf(av, bv.x, acc[i][0]);
                acc[i][1] = fmaf(av, bv.y, acc[i][1]);
                acc[i][2] = fmaf(av, bv.z, acc[i][2]);
                acc[i][3] = fmaf(av, bv.w, acc[i][3]);
            }
        }
    }

    int cbase = cb + tidx * 4;
    float4 bias = *(const float4*)(b2 + cbase);
#pragma unroll
    for (int i = 0; i < 4; i++) {
        int n = n0 + tidy * 4 + i;
        if (n < NN) {
            float4 o;
            o.x = silu(acc[i][0] + bias.x);
            o.y = silu(acc[i][1] + bias.y);
            o.z = silu(acc[i][2] + bias.z);
            o.w = silu(acc[i][3] + bias.w);
            *(float4*)(g_h2 + n * F2 + cbase) = o;
        }
    }
}

// ---------------- K8: segmented mean-pool (batch is sorted) ---------------
#define PN 512
__global__ void k_pool(const int* __restrict__ batch) {
    int c = threadIdx.x;        // 0..255; 0..199 handle cols, 200 handles counts
    int n0 = blockIdx.x * PN;
    int nend = min(n0 + PN, NN);
    if (c < F2) {
        float acc = 0.f; int curg = -1;
        for (int n = n0; n < nend; n++) {
            int g = batch[n];
            if (g != curg) {
                if (curg >= 0) atomicAdd(&g_sums[curg * F2 + c], acc);
                curg = g; acc = 0.f;
            }
            acc += g_h2[n * F2 + c];
        }
        if (curg >= 0) atomicAdd(&g_sums[curg * F2 + c], acc);
    } else if (c == F2) {
        float cnt = 0.f; int curg = -1;
        for (int n = n0; n < nend; n++) {
            int g = batch[n];
            if (g != curg) {
                if (curg >= 0) atomicAdd(&g_cnt[curg], cnt);
                curg = g; cnt = 0.f;
            }
            cnt += 1.0f;
        }
        if (curg >= 0) atomicAdd(&g_cnt[curg], cnt);
    }
}

// ---------------- K9: head: silu(pooled@Wl1+bl1)@Wl2+bl2 ------------------
__global__ void k_head(const float* __restrict__ Wl1, const float* __restrict__ bl1,
                       const float* __restrict__ Wl2, const float* __restrict__ bl2,
                       float* __restrict__ out) {
    __shared__ float sp[F2];
    __shared__ float sh[F1];
    int g = blockIdx.x;
    int tid = threadIdx.x;
    float cnt = fmaxf(g_cnt[g], 1.0f);
    for (int c = tid; c < F2; c += blockDim.x)
        sp[c] = g_sums[g * F2 + c] / cnt;
    __syncthreads();
    if (tid < F1) {
        float acc = bl1[tid];
        for (int c = 0; c < F2; c++)
            acc = fmaf(sp[c], Wl1[c * F1 + tid], acc);
        sh[tid] = silu(acc);
    }
    __syncthreads();
    if (tid == 0) {
        float s = bl2[0];
        for (int j = 0; j < F1; j++)
            s = fmaf(sh[j], Wl2[j], s);
        out[g] = s;
    }
}

// ---------------- launch ---------------------------------------------------
extern "C" void kernel_launch(void* const* d_in, const int* in_sizes, int n_in,
                              void* d_out, int out_size) {
    const float* x   = (const float*)d_in[0];
    const float* ea  = (const float*)d_in[1];
    const float* W1  = (const float*)d_in[2];
    const float* b1  = (const float*)d_in[3];
    const float* W2  = (const float*)d_in[4];
    const float* b2  = (const float*)d_in[5];
    const float* Wl1 = (const float*)d_in[6];
    const float* bl1 = (const float*)d_in[7];
    const float* Wl2 = (const float*)d_in[8];
    const float* bl2 = (const float*)d_in[9];
    const int*   ei  = (const int*)d_in[10];
    const int*   bat = (const int*)d_in[11];
    float* out = (float*)d_out;

    k_init<<<(NN + 255) / 256, 256>>>();
    k_deg<<<(NE + 255) / 256, 256>>>(ei, ea);
    k_dinv<<<(NN + 255) / 256, 256>>>(x);
    k_scatterX<<<(NE + 255) / 256, 256>>>(ei, ea, x);
    k_h1<<<(NN * 25 + 255) / 256, 256>>>(W1, b1);
    k_scatter1<<<(NE * 25 + 255) / 256, 256>>>(ei);
    k_gemm2<<<dim3((NN + BM - 1) / BM, F2 / BN), 160>>>(W2, b2);
    k_pool<<<(NN + PN - 1) / PN, 256>>>(bat);
    k_head<<<NG, 128>>>(Wl1, bl1, Wl2, bl2, out);
}